// round 1
// baseline (speedup 1.0000x reference)
#include <cuda_runtime.h>
#include <cstdint>

#define NQ 4
#define NL 6
#define NC 10
#define DIM 512
#define ROWS 128
#define THREADS 128
#define PI_F 3.14159265358979323846f

// U[i][j] (complex), stored column-major: d_U[j*16 + i]
__device__ float2 d_U[16 * 16];

// ---------------------------------------------------------------------------
// Setup kernel: build the 16x16 complex matrix of the 6-layer Rot+CNOT circuit.
// Thread j evolves basis state e_j through all layers.
// State index: idx = q0*8 + q1*4 + q2*2 + q3  (wire w -> bit (3-w))
// ---------------------------------------------------------------------------
__global__ void setup_U_kernel(const float* __restrict__ qw) {
    int j = threadIdx.x;
    if (j >= 16) return;

    float sre[16], simg[16];
#pragma unroll
    for (int i = 0; i < 16; i++) { sre[i] = 0.0f; simg[i] = 0.0f; }
    sre[j] = 1.0f;

#pragma unroll
    for (int l = 0; l < NL; l++) {
        // Rot gates on each wire
#pragma unroll
        for (int w = 0; w < NQ; w++) {
            float phi = qw[(l * NQ + w) * 3 + 0];
            float th  = qw[(l * NQ + w) * 3 + 1];
            float om  = qw[(l * NQ + w) * 3 + 2];
            float st, ct; sincosf(0.5f * th, &st, &ct);
            float sa, ca; sincosf(0.5f * (phi + om), &sa, &ca);
            float sb, cb; sincosf(0.5f * (phi - om), &sb, &cb);
            // g00 = e^{-i(phi+om)/2} c ; g01 = -e^{+i(phi-om)/2} s
            // g10 = e^{-i(phi-om)/2} s ; g11 = e^{+i(phi+om)/2} c
            float g00r =  ca * ct, g00i = -sa * ct;
            float g01r = -cb * st, g01i = -sb * st;
            float g10r =  cb * st, g10i = -sb * st;
            float g11r =  ca * ct, g11i =  sa * ct;
            int m = 1 << (3 - w);
#pragma unroll
            for (int i = 0; i < 16; i++) {
                if (i & m) continue;
                int i1 = i | m;
                float a0r = sre[i],  a0i = simg[i];
                float a1r = sre[i1], a1i = simg[i1];
                sre[i]   = g00r * a0r - g00i * a0i + g01r * a1r - g01i * a1i;
                simg[i]  = g00r * a0i + g00i * a0r + g01r * a1i + g01i * a1r;
                sre[i1]  = g10r * a0r - g10i * a0i + g11r * a1r - g11i * a1i;
                simg[i1] = g10r * a0i + g10i * a0r + g11r * a1i + g11i * a1r;
            }
        }
        // CNOT ring, range r = l % 3 + 1, applied w = 0..3 in order
        int r = l % (NQ - 1) + 1;
#pragma unroll
        for (int w = 0; w < NQ; w++) {
            int cmask = 1 << (3 - w);
            int tmask = 1 << (3 - ((w + r) & 3));
#pragma unroll
            for (int i = 0; i < 16; i++) {
                if ((i & cmask) && !(i & tmask)) {
                    int i1 = i | tmask;
                    float tr = sre[i];  sre[i]  = sre[i1];  sre[i1]  = tr;
                    float ti = simg[i]; simg[i] = simg[i1]; simg[i1] = ti;
                }
            }
        }
    }
#pragma unroll
    for (int i = 0; i < 16; i++) d_U[j * 16 + i] = make_float2(sre[i], simg[i]);
}

// ---------------------------------------------------------------------------
// Main fused kernel.
// Phase 1 (warp-per-row): pre = x @ W_pre.T, W_pre in registers, coalesced x.
// Phase 2 (thread-per-row): tanh -> angles -> product state v -> w = U v
//   -> probs -> Z-expectations -> post linear. Coalesced staged output.
// ---------------------------------------------------------------------------
__global__ __launch_bounds__(THREADS) void vqc_main_kernel(
    const float* __restrict__ x,
    const float* __restrict__ Wpre,
    const float* __restrict__ bpre,
    const float* __restrict__ Wpost,
    const float* __restrict__ bpost,
    float* __restrict__ out)
{
    __shared__ float2 sU[256];
    __shared__ float  spre[ROWS * 4];
    __shared__ float  souts[ROWS * NC];

    const int tid  = threadIdx.x;
    const int lane = tid & 31;
    const int wid  = tid >> 5;
    const int row0 = blockIdx.x * ROWS;

    // stage U into shared
    for (int i = tid; i < 256; i += THREADS) sU[i] = d_U[i];

    // --- Phase 1: GEMV, each warp handles 32 rows ---
    const float4* W4 = (const float4*)Wpre;   // [4][128] float4
    float4 wr[4][4];
#pragma unroll
    for (int w = 0; w < 4; w++)
#pragma unroll
        for (int jj = 0; jj < 4; jj++)
            wr[w][jj] = W4[w * 128 + jj * 32 + lane];

    const float4* x4 = (const float4*)x;      // row stride 128 float4
#pragma unroll 2
    for (int rr = 0; rr < 32; rr++) {
        int lrow = wid * 32 + rr;
        size_t base = (size_t)(row0 + lrow) * 128;
        float4 xv[4];
#pragma unroll
        for (int jj = 0; jj < 4; jj++) xv[jj] = x4[base + jj * 32 + lane];

        float acc[4] = {0.f, 0.f, 0.f, 0.f};
#pragma unroll
        for (int jj = 0; jj < 4; jj++) {
#pragma unroll
            for (int w = 0; w < 4; w++) {
                acc[w] = fmaf(xv[jj].x, wr[w][jj].x, acc[w]);
                acc[w] = fmaf(xv[jj].y, wr[w][jj].y, acc[w]);
                acc[w] = fmaf(xv[jj].z, wr[w][jj].z, acc[w]);
                acc[w] = fmaf(xv[jj].w, wr[w][jj].w, acc[w]);
            }
        }
#pragma unroll
        for (int off = 16; off > 0; off >>= 1) {
#pragma unroll
            for (int w = 0; w < 4; w++)
                acc[w] += __shfl_xor_sync(0xffffffffu, acc[w], off);
        }
        if (lane == 0) {
#pragma unroll
            for (int w = 0; w < 4; w++) spre[lrow * 4 + w] = acc[w];
        }
    }
    __syncthreads();

    // --- Phase 2: per-thread quantum evaluation for local row = tid ---
    float cw[4], sw[4];
#pragma unroll
    for (int w = 0; w < 4; w++) {
        float pre = spre[tid * 4 + w] + bpre[w];
        float ang = tanhf(pre) * PI_F;
        sincosf(0.5f * ang, &sw[w], &cw[w]);
    }
    // product state v[idx], idx = (q0*2+q1)*4 + (q2*2+q3)
    float p01[4], p23[4], v[16];
    p01[0] = cw[0] * cw[1]; p01[1] = cw[0] * sw[1];
    p01[2] = sw[0] * cw[1]; p01[3] = sw[0] * sw[1];
    p23[0] = cw[2] * cw[3]; p23[1] = cw[2] * sw[3];
    p23[2] = sw[2] * cw[3]; p23[3] = sw[2] * sw[3];
#pragma unroll
    for (int a = 0; a < 4; a++)
#pragma unroll
        for (int b = 0; b < 4; b++)
            v[a * 4 + b] = p01[a] * p23[b];

    // w = U v (v real)
    float wre[16], wim[16];
#pragma unroll
    for (int i = 0; i < 16; i++) { wre[i] = 0.0f; wim[i] = 0.0f; }
#pragma unroll
    for (int jcol = 0; jcol < 16; jcol++) {
        float vj = v[jcol];
        const float2* Uj = &sU[jcol * 16];
#pragma unroll
        for (int i = 0; i < 16; i++) {
            float2 u = Uj[i];
            wre[i] = fmaf(u.x, vj, wre[i]);
            wim[i] = fmaf(u.y, vj, wim[i]);
        }
    }

    // probs and Z expectations
    float pb[16];
#pragma unroll
    for (int i = 0; i < 16; i++) pb[i] = wre[i] * wre[i] + wim[i] * wim[i];

    float q[4];
#pragma unroll
    for (int w = 0; w < 4; w++) {
        int m = 1 << (3 - w);
        float s = 0.0f;
#pragma unroll
        for (int i = 0; i < 16; i++) s += (i & m) ? -pb[i] : pb[i];
        q[w] = s;
    }

    // post linear: out[c] = q . W_post[c] + b_post[c]
#pragma unroll
    for (int c = 0; c < NC; c++) {
        float o = bpost[c];
#pragma unroll
        for (int w = 0; w < 4; w++) o = fmaf(q[w], Wpost[c * 4 + w], o);
        souts[tid * NC + c] = o;
    }
    __syncthreads();

    // coalesced output
    size_t obase = (size_t)row0 * NC;
    for (int i = tid; i < ROWS * NC; i += THREADS)
        out[obase + i] = souts[i];
}

// ---------------------------------------------------------------------------
extern "C" void kernel_launch(void* const* d_in, const int* in_sizes, int n_in,
                              void* d_out, int out_size) {
    const float* x     = (const float*)d_in[0];
    const float* Wpre  = (const float*)d_in[1];
    const float* bpre  = (const float*)d_in[2];
    const float* qw    = (const float*)d_in[3];
    const float* Wpost = (const float*)d_in[4];
    const float* bpost = (const float*)d_in[5];
    float* out = (float*)d_out;

    int B = in_sizes[0] / DIM;   // 65536

    setup_U_kernel<<<1, 16>>>(qw);
    vqc_main_kernel<<<B / ROWS, THREADS>>>(x, Wpre, bpre, Wpost, bpost, out);
}

// round 2
// speedup vs baseline: 1.9993x; 1.9993x over previous
#include <cuda_runtime.h>
#include <cstdint>

#define NQ 4
#define NL 6
#define NC 10
#define DIM 512
#define PI_F 3.14159265358979323846f
#define MAXB 65536

// U[i][j] (complex), column-major: d_U[j*16 + i]
__device__ float2 d_U[256];
// pre-activations staging (pre + bias), [B][4]
__device__ float d_pre[MAXB * 4];

// packed f32x2 FMA: d = a*b + c elementwise on (lo,hi) pairs
__device__ __forceinline__ void fma2(unsigned long long& d, unsigned long long a,
                                     unsigned long long b, unsigned long long c) {
    asm("fma.rn.f32x2 %0, %1, %2, %3;" : "=l"(d) : "l"(a), "l"(b), "l"(c));
}

// ---------------------------------------------------------------------------
// Setup: build 16x16 complex circuit matrix U.
// Phase A: 24 threads compute gate coefficient matrices in parallel.
// Phase B: 8 warps, each evolves 2 basis columns; lane = sub*16 + i holds
//          amplitude i of column j = 2*warp + sub. Butterflies via shfl_xor.
// ---------------------------------------------------------------------------
__global__ void setup_U_kernel(const float* __restrict__ qw) {
    __shared__ float sg[24][8];   // g00r,g00i,g01r,g01i,g10r,g10i,g11r,g11i
    int tid = threadIdx.x;

    if (tid < 24) {
        float phi = qw[tid * 3 + 0];
        float th  = qw[tid * 3 + 1];
        float om  = qw[tid * 3 + 2];
        float st, ct; sincosf(0.5f * th, &st, &ct);
        float sa, ca; sincosf(0.5f * (phi + om), &sa, &ca);
        float sb, cb; sincosf(0.5f * (phi - om), &sb, &cb);
        sg[tid][0] =  ca * ct;  sg[tid][1] = -sa * ct;   // g00
        sg[tid][2] = -cb * st;  sg[tid][3] = -sb * st;   // g01
        sg[tid][4] =  cb * st;  sg[tid][5] = -sb * st;   // g10
        sg[tid][6] =  ca * ct;  sg[tid][7] =  sa * ct;   // g11
    }
    __syncthreads();

    int lane = tid & 31;
    int warp = tid >> 5;
    int i = lane & 15;
    int j = 2 * warp + (lane >> 4);

    float re = (i == j) ? 1.0f : 0.0f;
    float im = 0.0f;

#pragma unroll
    for (int l = 0; l < NL; l++) {
#pragma unroll
        for (int w = 0; w < NQ; w++) {
            const float* g = sg[l * NQ + w];
            int m = 8 >> w;
            float pre_ = __shfl_xor_sync(0xffffffffu, re, m);
            float pim  = __shfl_xor_sync(0xffffffffu, im, m);
            bool low = (i & m) == 0;
            float orr = low ? g[0] : g[6];   // own coeff
            float oii = low ? g[1] : g[7];
            float crr = low ? g[2] : g[4];   // cross coeff
            float cii = low ? g[3] : g[5];
            float nre = orr * re - oii * im + crr * pre_ - cii * pim;
            float nim = orr * im + oii * re + crr * pim + cii * pre_;
            re = nre; im = nim;
        }
        int r = l % (NQ - 1) + 1;
#pragma unroll
        for (int w = 0; w < NQ; w++) {
            int cmask = 8 >> w;
            int tmask = 8 >> ((w + r) & 3);
            int src_i = (i & cmask) ? (i ^ tmask) : i;
            int srcLane = (lane & 16) | src_i;
            re = __shfl_sync(0xffffffffu, re, srcLane);
            im = __shfl_sync(0xffffffffu, im, srcLane);
        }
    }
    d_U[j * 16 + i] = make_float2(re, im);
}

// ---------------------------------------------------------------------------
// GEMV kernel: pre[b][w] = x[b] . W_pre[w] + b_pre[w]
// 256 threads = 8 warps; warp owns 16 rows. W in registers (64 regs/lane).
// ---------------------------------------------------------------------------
__global__ __launch_bounds__(256) void gemv_kernel(
    const float* __restrict__ x,
    const float* __restrict__ Wpre,
    const float* __restrict__ bpre)
{
    const int lane = threadIdx.x & 31;
    const int wid  = threadIdx.x >> 5;
    const int row0 = (blockIdx.x * 8 + wid) * 16;

    const float4* W4 = (const float4*)Wpre;   // [4][128] float4
    float4 wr[4][4];
#pragma unroll
    for (int w = 0; w < 4; w++)
#pragma unroll
        for (int jj = 0; jj < 4; jj++)
            wr[w][jj] = W4[w * 128 + jj * 32 + lane];

    float b0 = bpre[0], b1 = bpre[1], b2 = bpre[2], b3 = bpre[3];

    const float4* x4 = (const float4*)x;
    // prefetch row 0
    float4 xv[4];
    {
        size_t base = (size_t)row0 * 128;
#pragma unroll
        for (int jj = 0; jj < 4; jj++) xv[jj] = x4[base + jj * 32 + lane];
    }

#pragma unroll
    for (int rr = 0; rr < 16; rr++) {
        float4 nx[4];
        if (rr + 1 < 16) {
            size_t base = (size_t)(row0 + rr + 1) * 128;
#pragma unroll
            for (int jj = 0; jj < 4; jj++) nx[jj] = x4[base + jj * 32 + lane];
        }

        float acc[4] = {0.f, 0.f, 0.f, 0.f};
#pragma unroll
        for (int jj = 0; jj < 4; jj++) {
#pragma unroll
            for (int w = 0; w < 4; w++) {
                acc[w] = fmaf(xv[jj].x, wr[w][jj].x, acc[w]);
                acc[w] = fmaf(xv[jj].y, wr[w][jj].y, acc[w]);
                acc[w] = fmaf(xv[jj].z, wr[w][jj].z, acc[w]);
                acc[w] = fmaf(xv[jj].w, wr[w][jj].w, acc[w]);
            }
        }
#pragma unroll
        for (int off = 16; off > 0; off >>= 1)
#pragma unroll
            for (int w = 0; w < 4; w++)
                acc[w] += __shfl_xor_sync(0xffffffffu, acc[w], off);

        if (lane == 0) {
            float4 o = make_float4(acc[0] + b0, acc[1] + b1, acc[2] + b2, acc[3] + b3);
            ((float4*)d_pre)[row0 + rr] = o;
        }
#pragma unroll
        for (int jj = 0; jj < 4; jj++) xv[jj] = nx[jj];
    }
}

// ---------------------------------------------------------------------------
// Quantum kernel: thread-per-row. angles -> product state -> U v -> probs ->
// Z expectations -> post linear. Output staged in smem for coalesced stores.
// ---------------------------------------------------------------------------
#define QT 256
__global__ __launch_bounds__(QT) void quantum_kernel(
    const float* __restrict__ Wpost,
    const float* __restrict__ bpost,
    float* __restrict__ out)
{
    __shared__ float2 sU[256];
    __shared__ float  souts[QT * NC];

    const int tid  = threadIdx.x;
    const int row  = blockIdx.x * QT + tid;

    for (int i = tid; i < 256; i += QT) sU[i] = d_U[i];
    __syncthreads();

    float4 pre = ((const float4*)d_pre)[row];
    float cw[4], sw[4];
    {
        float a0 = tanhf(pre.x) * PI_F; sincosf(0.5f * a0, &sw[0], &cw[0]);
        float a1 = tanhf(pre.y) * PI_F; sincosf(0.5f * a1, &sw[1], &cw[1]);
        float a2 = tanhf(pre.z) * PI_F; sincosf(0.5f * a2, &sw[2], &cw[2]);
        float a3 = tanhf(pre.w) * PI_F; sincosf(0.5f * a3, &sw[3], &cw[3]);
    }

    // product state v[idx], idx = q0*8 + q1*4 + q2*2 + q3
    float p01[4], p23[4], v[16];
    p01[0] = cw[0] * cw[1]; p01[1] = cw[0] * sw[1];
    p01[2] = sw[0] * cw[1]; p01[3] = sw[0] * sw[1];
    p23[0] = cw[2] * cw[3]; p23[1] = cw[2] * sw[3];
    p23[2] = sw[2] * cw[3]; p23[3] = sw[2] * sw[3];
#pragma unroll
    for (int a = 0; a < 4; a++)
#pragma unroll
        for (int b = 0; b < 4; b++)
            v[a * 4 + b] = p01[a] * p23[b];

    // w = U v, packed (re,im) f32x2 accumulate
    unsigned long long acc[16];
#pragma unroll
    for (int i = 0; i < 16; i++) acc[i] = 0ull;

    const unsigned long long* sU64 = (const unsigned long long*)sU;
#pragma unroll
    for (int jcol = 0; jcol < 16; jcol++) {
        unsigned long long vj2;
        asm("mov.b64 %0, {%1, %1};" : "=l"(vj2) : "r"(__float_as_uint(v[jcol])));
#pragma unroll
        for (int i = 0; i < 16; i++)
            fma2(acc[i], sU64[jcol * 16 + i], vj2, acc[i]);
    }

    // probs and Z expectations
    float pb[16];
#pragma unroll
    for (int i = 0; i < 16; i++) {
        unsigned int lo, hi;
        asm("mov.b64 {%0, %1}, %2;" : "=r"(lo), "=r"(hi) : "l"(acc[i]));
        float re = __uint_as_float(lo), im = __uint_as_float(hi);
        pb[i] = re * re + im * im;
    }

    float q[4];
#pragma unroll
    for (int w = 0; w < 4; w++) {
        int m = 8 >> w;
        float s = 0.0f;
#pragma unroll
        for (int i = 0; i < 16; i++) s += (i & m) ? -pb[i] : pb[i];
        q[w] = s;
    }

#pragma unroll
    for (int c = 0; c < NC; c++) {
        float o = bpost[c];
#pragma unroll
        for (int w = 0; w < 4; w++) o = fmaf(q[w], Wpost[c * 4 + w], o);
        souts[tid * NC + c] = o;
    }
    __syncthreads();

    size_t obase = (size_t)blockIdx.x * QT * NC;
    for (int i = tid; i < QT * NC; i += QT)
        out[obase + i] = souts[i];
}

// ---------------------------------------------------------------------------
extern "C" void kernel_launch(void* const* d_in, const int* in_sizes, int n_in,
                              void* d_out, int out_size) {
    const float* x     = (const float*)d_in[0];
    const float* Wpre  = (const float*)d_in[1];
    const float* bpre  = (const float*)d_in[2];
    const float* qw    = (const float*)d_in[3];
    const float* Wpost = (const float*)d_in[4];
    const float* bpost = (const float*)d_in[5];
    float* out = (float*)d_out;

    int B = in_sizes[0] / DIM;   // 65536

    setup_U_kernel<<<1, 256>>>(qw);
    gemv_kernel<<<B / 128, 256>>>(x, Wpre, bpre);
    quantum_kernel<<<B / QT, QT>>>(Wpost, bpost, out);
}

// round 3
// speedup vs baseline: 2.7863x; 1.3936x over previous
#include <cuda_runtime.h>
#include <cstdint>

#define NQ 4
#define NL 6
#define NC 10
#define DIM 512
#define PI_F 3.14159265358979323846f
#define HPI_F 1.57079632679489661923f

#define THREADS 256
#define ROWS 256   // rows per block == THREADS (thread-per-row in phase 2)

// packed f32x2 FMA: d = a*b + c elementwise on (lo,hi) pairs
__device__ __forceinline__ void fma2(unsigned long long& d, unsigned long long a,
                                     unsigned long long b, unsigned long long c) {
    asm("fma.rn.f32x2 %0, %1, %2, %3;" : "=l"(d) : "l"(a), "l"(b), "l"(c));
}

// ---------------------------------------------------------------------------
// Single fused kernel.
// Phase 0: all 8 warps cooperatively build the 16x16 complex circuit matrix U
//          (warp w evolves basis columns 2w, 2w+1; lane = sub*16 + i).
// Phase 1: GEMV. warp w computes rows w*32..w*32+31; per row 4x LDG.128/lane,
//          FMA into 4 accs, 2-level shfl reduce, lanes 0-7 write partials.
// Phase 2: thread-per-row: sum partials -> pre -> tanh -> angles -> product
//          state v -> U v (f32x2) -> probs -> Z exps -> post linear.
// ---------------------------------------------------------------------------
__global__ __launch_bounds__(THREADS, 2) void vqc_fused_kernel(
    const float* __restrict__ x,
    const float* __restrict__ Wpre,
    const float* __restrict__ bpre,
    const float* __restrict__ qw,
    const float* __restrict__ Wpost,
    const float* __restrict__ bpost,
    float* __restrict__ out)
{
    __shared__ float  sg[24][8];            // gate coeffs
    __shared__ float2 sU[256];              // U column-major [j][i]
    __shared__ float4 spart[ROWS * 8];      // 32KB partial sums [row][group]
    __shared__ float  souts[ROWS * NC];     // 10KB staged output

    const int tid  = threadIdx.x;
    const int lane = tid & 31;
    const int warp = tid >> 5;
    const int row0 = blockIdx.x * ROWS;

    // ---- issue first-row GEMV prefetch before the U chain (independent) ----
    const float4* x4 = (const float4*)x;
    const int wrow0 = row0 + warp * 32;
    float4 xv[4];
    {
        size_t base = (size_t)wrow0 * 128;
#pragma unroll
        for (int jj = 0; jj < 4; jj++) xv[jj] = x4[base + jj * 32 + lane];
    }
    // W_pre into registers
    const float4* W4 = (const float4*)Wpre;   // [4][128] float4
    float4 wr[4][4];
#pragma unroll
    for (int w = 0; w < 4; w++)
#pragma unroll
        for (int jj = 0; jj < 4; jj++)
            wr[w][jj] = W4[w * 128 + jj * 32 + lane];

    // ---- Phase 0: build U ----
    if (tid < 24) {
        float phi = qw[tid * 3 + 0];
        float th  = qw[tid * 3 + 1];
        float om  = qw[tid * 3 + 2];
        float st, ct; sincosf(0.5f * th, &st, &ct);
        float sa, ca; sincosf(0.5f * (phi + om), &sa, &ca);
        float sb, cb; sincosf(0.5f * (phi - om), &sb, &cb);
        sg[tid][0] =  ca * ct;  sg[tid][1] = -sa * ct;   // g00
        sg[tid][2] = -cb * st;  sg[tid][3] = -sb * st;   // g01
        sg[tid][4] =  cb * st;  sg[tid][5] = -sb * st;   // g10
        sg[tid][6] =  ca * ct;  sg[tid][7] =  sa * ct;   // g11
    }
    __syncthreads();
    {
        int i = lane & 15;
        int j = 2 * warp + (lane >> 4);
        float re = (i == j) ? 1.0f : 0.0f;
        float im = 0.0f;
#pragma unroll
        for (int l = 0; l < NL; l++) {
#pragma unroll
            for (int w = 0; w < NQ; w++) {
                const float* g = sg[l * NQ + w];
                int m = 8 >> w;
                float pre_ = __shfl_xor_sync(0xffffffffu, re, m);
                float pim  = __shfl_xor_sync(0xffffffffu, im, m);
                bool low = (i & m) == 0;
                float orr = low ? g[0] : g[6];
                float oii = low ? g[1] : g[7];
                float crr = low ? g[2] : g[4];
                float cii = low ? g[3] : g[5];
                float nre = orr * re - oii * im + crr * pre_ - cii * pim;
                float nim = orr * im + oii * re + crr * pim + cii * pre_;
                re = nre; im = nim;
            }
            int r = l % (NQ - 1) + 1;
#pragma unroll
            for (int w = 0; w < NQ; w++) {
                int cmask = 8 >> w;
                int tmask = 8 >> ((w + r) & 3);
                int src_i = (i & cmask) ? (i ^ tmask) : i;
                int srcLane = (lane & 16) | src_i;
                re = __shfl_sync(0xffffffffu, re, srcLane);
                im = __shfl_sync(0xffffffffu, im, srcLane);
            }
        }
        sU[j * 16 + i] = make_float2(re, im);
    }

    // ---- Phase 1: GEMV (no syncthreads needed before: sU/spart disjoint) ----
#pragma unroll 4
    for (int rr = 0; rr < 32; rr++) {
        float4 nx[4];
        if (rr + 1 < 32) {
            size_t base = (size_t)(wrow0 + rr + 1) * 128;
#pragma unroll
            for (int jj = 0; jj < 4; jj++) nx[jj] = x4[base + jj * 32 + lane];
        }
        float acc[4] = {0.f, 0.f, 0.f, 0.f};
#pragma unroll
        for (int jj = 0; jj < 4; jj++) {
#pragma unroll
            for (int w = 0; w < 4; w++) {
                acc[w] = fmaf(xv[jj].x, wr[w][jj].x, acc[w]);
                acc[w] = fmaf(xv[jj].y, wr[w][jj].y, acc[w]);
                acc[w] = fmaf(xv[jj].z, wr[w][jj].z, acc[w]);
                acc[w] = fmaf(xv[jj].w, wr[w][jj].w, acc[w]);
            }
        }
        // 2-level reduce: lane holds sum over {lane, ^8, ^16, ^24}
#pragma unroll
        for (int w = 0; w < 4; w++) {
            acc[w] += __shfl_xor_sync(0xffffffffu, acc[w], 16);
            acc[w] += __shfl_xor_sync(0xffffffffu, acc[w], 8);
        }
        if (lane < 8) {
            int lrow = warp * 32 + rr;
            spart[lrow * 8 + lane] = make_float4(acc[0], acc[1], acc[2], acc[3]);
        }
#pragma unroll
        for (int jj = 0; jj < 4; jj++) xv[jj] = nx[jj];
    }
    __syncthreads();

    // ---- Phase 2: thread-per-row quantum ----
    float4 pre4 = make_float4(bpre[0], bpre[1], bpre[2], bpre[3]);
#pragma unroll
    for (int k = 0; k < 8; k++) {
        float4 p = spart[tid * 8 + ((tid + k) & 7)];   // bank-swizzled
        pre4.x += p.x; pre4.y += p.y; pre4.z += p.z; pre4.w += p.w;
    }

    float cw[4], sw[4];
    {
        float pv[4] = {pre4.x, pre4.y, pre4.z, pre4.w};
#pragma unroll
        for (int w = 0; w < 4; w++) {
            float e = __expf(2.0f * pv[w]);
            float t = 1.0f - __fdividef(2.0f, e + 1.0f);   // tanh(pre)
            float h = HPI_F * t;                            // angle/2
            sw[w] = __sinf(h);
            cw[w] = __cosf(h);
        }
    }

    // product state v[idx], idx = q0*8 + q1*4 + q2*2 + q3
    float p01[4], p23[4], v[16];
    p01[0] = cw[0] * cw[1]; p01[1] = cw[0] * sw[1];
    p01[2] = sw[0] * cw[1]; p01[3] = sw[0] * sw[1];
    p23[0] = cw[2] * cw[3]; p23[1] = cw[2] * sw[3];
    p23[2] = sw[2] * cw[3]; p23[3] = sw[2] * sw[3];
#pragma unroll
    for (int a = 0; a < 4; a++)
#pragma unroll
        for (int b = 0; b < 4; b++)
            v[a * 4 + b] = p01[a] * p23[b];

    // w = U v, packed (re,im) f32x2
    unsigned long long acc64[16];
#pragma unroll
    for (int i = 0; i < 16; i++) acc64[i] = 0ull;
    const unsigned long long* sU64 = (const unsigned long long*)sU;
#pragma unroll
    for (int jcol = 0; jcol < 16; jcol++) {
        unsigned long long vj2;
        asm("mov.b64 %0, {%1, %1};" : "=l"(vj2) : "r"(__float_as_uint(v[jcol])));
#pragma unroll
        for (int i = 0; i < 16; i++)
            fma2(acc64[i], sU64[jcol * 16 + i], vj2, acc64[i]);
    }

    float pb[16];
#pragma unroll
    for (int i = 0; i < 16; i++) {
        unsigned int lo, hi;
        asm("mov.b64 {%0, %1}, %2;" : "=r"(lo), "=r"(hi) : "l"(acc64[i]));
        float re = __uint_as_float(lo), im = __uint_as_float(hi);
        pb[i] = re * re + im * im;
    }

    float q[4];
#pragma unroll
    for (int w = 0; w < 4; w++) {
        int m = 8 >> w;
        float s = 0.0f;
#pragma unroll
        for (int i = 0; i < 16; i++) s += (i & m) ? -pb[i] : pb[i];
        q[w] = s;
    }

#pragma unroll
    for (int c = 0; c < NC; c++) {
        float o = bpost[c];
#pragma unroll
        for (int w = 0; w < 4; w++) o = fmaf(q[w], Wpost[c * 4 + w], o);
        souts[tid * NC + c] = o;
    }
    __syncthreads();

    // coalesced output
    size_t obase = (size_t)row0 * NC;
    for (int i = tid; i < ROWS * NC; i += THREADS)
        out[obase + i] = souts[i];
}

// ---------------------------------------------------------------------------
extern "C" void kernel_launch(void* const* d_in, const int* in_sizes, int n_in,
                              void* d_out, int out_size) {
    const float* x     = (const float*)d_in[0];
    const float* Wpre  = (const float*)d_in[1];
    const float* bpre  = (const float*)d_in[2];
    const float* qw    = (const float*)d_in[3];
    const float* Wpost = (const float*)d_in[4];
    const float* bpost = (const float*)d_in[5];
    float* out = (float*)d_out;

    int B = in_sizes[0] / DIM;   // 65536
    vqc_fused_kernel<<<B / ROWS, THREADS>>>(x, Wpre, bpre, qw, Wpost, bpost, out);
}